// round 1
// baseline (speedup 1.0000x reference)
#include <cuda_runtime.h>
#include <math.h>

// ---------------- problem constants ----------------
#define NS    5
#define NG    70
#define NBC   40
#define HP    150          // padded grid (70 + 2*40)
#define NT    1000
#define ISZ   41           // source row (padded coords)
#define IGZ   41           // receiver row
// smem field layout: 2-wide halo each side, extra x pad for vector groups
#define SW    156          // smem row stride (floats): 2 halo + 150 + 2 halo + 2 pad
#define SHR   154          // smem rows: 2 + 150 + 2
#define CW    152          // coeff row stride (150 + 2 zero pad)
#define GPR   38           // 4-wide groups per row (covers 152 cells, last 2 garbage)
#define TOTG  (HP * GPR)   // 5700 groups
#define SMEM_BYTES ((2 * SHR * SW + NT) * 4)

__device__ float g_temp1[2 * HP * CW];
__device__ float g_temp2[2 * HP * CW];
__device__ float g_alpha[2 * HP * CW];
__device__ float g_src[NT];
__device__ float g_bsrc[2 * NS];

__constant__ int c_isx[NS] = {40, 57, 74, 92, 109};  // np.around (half-to-even) of linspace

// ---------------- init: coefficients, source wavelet, bsrc ----------------
__global__ void fwi_init(const float* __restrict__ v) {
    const int b   = blockIdx.x;          // 0..1
    const int tid = threadIdx.x;         // 256 threads
    __shared__ float red[256];

    const float* vb = v + b * 70 * 70;

    // velmin over this batch
    float m = 1e30f;
    for (int k = tid; k < 70 * 70; k += 256) m = fminf(m, vb[k]);
    red[tid] = m;
    __syncthreads();
    for (int s = 128; s > 0; s >>= 1) {
        if (tid < s) red[tid] = fminf(red[tid], red[tid + s]);
        __syncthreads();
    }
    const float vmin  = red[0];
    // kappa = 3*vmin*ln(1e7) / (2*(NBC-1)*DX)   (f32 op order like jax)
    const float kappa = ((3.0f * vmin) * 16.118095650958319f) / 780.0f;

    for (int k = tid; k < HP * CW; k += 256) {
        const int i = k / CW;
        const int j = k - i * CW;
        float t1 = 0.f, t2 = 0.f, al = 0.f;
        if (j < HP) {
            const int vi = min(max(i - NBC, 0), 69);
            const int vj = min(max(j - NBC, 0), 69);
            const float vp = vb[vi * 70 + vj];
            const float a  = vp * 0.001f / 10.0f;   // v*DT/DX
            al = a * a;
            // damping ramp: last .at[].set wins -> x-sides take priority over z-sides
            float r2 = 0.f;
            int rk = -1;
            if      (j < NBC)        rk = (NBC - 1) - j;   // flipped
            else if (j >= HP - NBC)  rk = j - (HP - NBC);
            else if (i < NBC)        rk = (NBC - 1) - i;
            else if (i >= HP - NBC)  rk = i - (HP - NBC);
            if (rk >= 0) {
                const float t = ((float)rk * 10.0f) / 390.0f;
                r2 = t * t;
            }
            const float kdt = (kappa * r2) * 0.001f;   // damp * DT
            t1 = 2.0f - 5.0f * al - kdt;               // 2 + 2*C1*alpha - kappa_dt
            t2 = 1.0f - kdt;
        }
        const int off = b * HP * CW + k;
        g_temp1[off] = t1;
        g_temp2[off] = t2;
        g_alpha[off] = al;
    }

    // bsrc[b][s] = (v_pad[ISZ, isx]*DT)^2
    if (tid < NS) {
        const int isxs = c_isx[tid];
        const int vi = min(max(ISZ  - NBC, 0), 69);
        const int vj = min(max(isxs - NBC, 0), 69);
        const float bv = vb[vi * 70 + vj] * 0.001f;
        g_bsrc[b * NS + tid] = bv * bv;
    }

    // ricker wavelet (double math, matches numpy): nw=147, nc=73
    if (b == 0) {
        for (int t = tid; t < NT; t += 256) {
            float w = 0.f;
            if (t < 147) {
                const double a  = (73.0 - (double)t) * 15.0 * 0.001 * 3.141592653589793;
                const double be = a * a;
                w = (float)((1.0 - 2.0 * be) * exp(-be));
            }
            g_src[t] = w;
        }
    }
}

// ---------------- main persistent kernel: one CTA per (b,s) field ----------------
__global__ void __launch_bounds__(1024, 1)
fwi_kernel(float* __restrict__ out) {
    extern __shared__ float sm[];
    float* bufA = sm;
    float* bufB = sm + SHR * SW;
    float* srcs = sm + 2 * SHR * SW;

    const int tid = threadIdx.x;
    const int b   = blockIdx.x / NS;
    const int s   = blockIdx.x - b * NS;

    // zero both field buffers (halos + pads included)
    for (int k = tid; k < 2 * SHR * SW; k += 1024) sm[k] = 0.f;
    for (int k = tid; k < NT; k += 1024) srcs[k] = g_src[k];
    __syncthreads();

    const float* __restrict__ T1 = g_temp1 + b * HP * CW;
    const float* __restrict__ T2 = g_temp2 + b * HP * CW;
    const float* __restrict__ AL = g_alpha + b * HP * CW;
    const int   isxs  = c_isx[s];
    const float bsrcv = g_bsrc[b * NS + s];
    float* __restrict__ orow = out + (size_t)(b * NS + s) * NT * NG;

    const float C2v = (float)( 4.0 / 3.0);
    const float C3v = (float)(-1.0 / 12.0);

    float* pold = bufA;   // p0 (t-1); pnew written here
    float* pcur = bufB;   // p1 (t)

    for (int t = 0; t < NT; ++t) {
        const float srcval = bsrcv * srcs[t];

        // ---- phase A: pnew = temp1*p1 - temp2*p0 + alpha*lap(p1), 4 cells/group ----
        for (int gi = tid; gi < TOTG; gi += 1024) {
            const int i  = gi / GPR;
            const int g  = gi - i * GPR;
            const int j0 = g * 4;
            const int base = (i + 2) * SW + j0;          // smem x of logical j0-2

            const float4 a0 = *(const float4*)(pcur + base);        // j0-2..j0+1
            const float4 a1 = *(const float4*)(pcur + base + 4);    // j0+2..j0+5
            const float2 m2a = *(const float2*)(pcur + base - 2 * SW + 2);
            const float2 m2b = *(const float2*)(pcur + base - 2 * SW + 4);
            const float2 m1a = *(const float2*)(pcur + base -     SW + 2);
            const float2 m1b = *(const float2*)(pcur + base -     SW + 4);
            const float2 p1a = *(const float2*)(pcur + base +     SW + 2);
            const float2 p1b = *(const float2*)(pcur + base +     SW + 4);
            const float2 p2a = *(const float2*)(pcur + base + 2 * SW + 2);
            const float2 p2b = *(const float2*)(pcur + base + 2 * SW + 4);
            const float2 o0  = *(const float2*)(pold + base + 2);
            const float2 o1  = *(const float2*)(pold + base + 4);

            const int cb = i * CW + j0;
            const float4 t1 = *(const float4*)(T1 + cb);
            const float4 t2 = *(const float4*)(T2 + cb);
            const float4 al = *(const float4*)(AL + cb);

            const float l0 = C2v * (a0.y + a0.w + m1a.x + p1a.x)
                           + C3v * (a0.x + a1.x + m2a.x + p2a.x);
            const float l1 = C2v * (a0.z + a1.x + m1a.y + p1a.y)
                           + C3v * (a0.y + a1.y + m2a.y + p2a.y);
            const float l2 = C2v * (a0.w + a1.y + m1b.x + p1b.x)
                           + C3v * (a0.z + a1.z + m2b.x + p2b.x);
            const float l3 = C2v * (a1.x + a1.z + m1b.y + p1b.y)
                           + C3v * (a0.w + a1.w + m2b.y + p2b.y);

            float n0 = t1.x * a0.z - t2.x * o0.x + al.x * l0;
            float n1 = t1.y * a0.w - t2.y * o0.y + al.y * l1;
            float n2 = t1.z * a1.x - t2.z * o1.x + al.z * l2;
            float n3 = t1.w * a1.y - t2.w * o1.y + al.w * l3;

            if (i == ISZ) {
                const int d = isxs - j0;
                if      (d == 0) n0 += srcval;
                else if (d == 1) n1 += srcval;
                else if (d == 2) n2 += srcval;
                else if (d == 3) n3 += srcval;
            }

            *(float2*)(pold + base + 2) = make_float2(n0, n1);
            *(float2*)(pold + base + 4) = make_float2(n2, n3);
        }
        __syncthreads();

        // ---- phase B: refresh periodic halos of pnew (=pold) + record receivers ----
        float* pn = pold;
        for (int k = tid; k < 600 + 600 + NG; k += 1024) {
            if (k < 600) {                       // z-halo rows, interior x only
                const int r  = k / 150;
                const int x  = k - r * 150 + 2;  // x in [2,151]
                const int dz = (r < 2) ? r : (150 + r);        // 0,1,152,153
                const int sz = (r < 2) ? (150 + r) : r;        // 150,151,2,3
                pn[dz * SW + x] = pn[sz * SW + x];
            } else if (k < 1200) {               // x-halo cols, interior z only
                const int k2 = k - 600;
                const int c  = k2 / 150;
                const int z  = k2 - c * 150 + 2; // z in [2,151]
                const int dx = (c < 2) ? c : (150 + c);
                const int sx = (c < 2) ? (150 + c) : c;
                pn[z * SW + dx] = pn[z * SW + sx];
            } else {                             // receivers: igx = 40..109
                const int gg = k - 1200;
                orow[t * NG + gg] = pn[(IGZ + 2) * SW + (NBC + gg + 2)];
            }
        }
        __syncthreads();

        float* tmp = pold; pold = pcur; pcur = tmp;
    }
}

// ---------------- launch ----------------
extern "C" void kernel_launch(void* const* d_in, const int* in_sizes, int n_in,
                              void* d_out, int out_size) {
    const float* v = (const float*)d_in[0];
    float* out = (float*)d_out;

    cudaFuncSetAttribute(fwi_kernel, cudaFuncAttributeMaxDynamicSharedMemorySize,
                         SMEM_BYTES);

    fwi_init<<<2, 256>>>(v);
    fwi_kernel<<<2 * NS, 1024, SMEM_BYTES>>>(out);
}

// round 3
// speedup vs baseline: 4.7498x; 4.7498x over previous
#include <cuda_runtime.h>
#include <cstdint>
#include <math.h>

// ---------------- problem constants ----------------
#define NS    5
#define NG    70
#define NBC   40
#define HP    150          // padded grid (70 + 2*40)
#define NT    1000
#define ISZ   41           // source row (padded coords)
#define IGZ   41           // receiver row
#define SW    156          // smem row stride (floats): 2 halo + 150 + 2 halo + 2 pad
#define CW    152          // coeff row stride (150 + 2 zero pad)
#define GPR   38           // 4-wide groups per row
#define CLUSTER 8
#define TPB   512
#define MAXNR 19
#define ROWS_S (MAXNR + 4)     // 23 smem rows per CTA (2 halo each side)

#define SMEM_FLOATS (2 * ROWS_S * SW + 3 * MAXNR * CW + NT)
#define SMEM_BYTES  (SMEM_FLOATS * 4)

__device__ float g_temp1[2 * HP * CW];
__device__ float g_temp2[2 * HP * CW];
__device__ float g_alpha[2 * HP * CW];
__device__ float g_src[NT];
__device__ float g_bsrc[2 * NS];

__constant__ int c_isx[NS]        = {40, 57, 74, 92, 109};
__constant__ int c_start[CLUSTER] = {0, 19, 38, 57, 76, 95, 114, 132};
__constant__ int c_nr[CLUSTER]    = {19, 19, 19, 19, 19, 19, 18, 18};

// ---------------- ptx helpers ----------------
__device__ __forceinline__ unsigned int smem_u32(const void* p) {
    return (unsigned int)__cvta_generic_to_shared(p);
}
__device__ __forceinline__ unsigned int mapa_u32(unsigned int a, unsigned int r) {
    unsigned int d;
    asm("mapa.shared::cluster.u32 %0, %1, %2;" : "=r"(d) : "r"(a), "r"(r));
    return d;
}
__device__ __forceinline__ float ld_cluster(unsigned int a) {
    float v;
    asm volatile("ld.shared::cluster.f32 %0, [%1];" : "=f"(v) : "r"(a));
    return v;
}
__device__ __forceinline__ unsigned int my_ctarank() {
    unsigned int r;
    asm("mov.u32 %0, %%cluster_ctarank;" : "=r"(r));
    return r;
}

// ---------------- init: coefficients, source wavelet, bsrc ----------------
__global__ void fwi_init(const float* __restrict__ v) {
    const int b   = blockIdx.x;          // 0..1
    const int tid = threadIdx.x;         // 256 threads
    __shared__ float red[256];

    const float* vb = v + b * 70 * 70;

    float m = 1e30f;
    for (int k = tid; k < 70 * 70; k += 256) m = fminf(m, vb[k]);
    red[tid] = m;
    __syncthreads();
    for (int s = 128; s > 0; s >>= 1) {
        if (tid < s) red[tid] = fminf(red[tid], red[tid + s]);
        __syncthreads();
    }
    const float vmin  = red[0];
    const float kappa = ((3.0f * vmin) * 16.118095650958319f) / 780.0f;

    for (int k = tid; k < HP * CW; k += 256) {
        const int i = k / CW;
        const int j = k - i * CW;
        float t1 = 0.f, t2 = 0.f, al = 0.f;
        if (j < HP) {
            const int vi = min(max(i - NBC, 0), 69);
            const int vj = min(max(j - NBC, 0), 69);
            const float vp = vb[vi * 70 + vj];
            const float a  = vp * 0.001f / 10.0f;
            al = a * a;
            float r2 = 0.f;
            int rk = -1;
            if      (j < NBC)        rk = (NBC - 1) - j;
            else if (j >= HP - NBC)  rk = j - (HP - NBC);
            else if (i < NBC)        rk = (NBC - 1) - i;
            else if (i >= HP - NBC)  rk = i - (HP - NBC);
            if (rk >= 0) {
                const float t = ((float)rk * 10.0f) / 390.0f;
                r2 = t * t;
            }
            const float kdt = (kappa * r2) * 0.001f;
            t1 = 2.0f - 5.0f * al - kdt;
            t2 = 1.0f - kdt;
        }
        const int off = b * HP * CW + k;
        g_temp1[off] = t1;
        g_temp2[off] = t2;
        g_alpha[off] = al;
    }

    if (tid < NS) {
        const int isxs = c_isx[tid];
        const int vi = min(max(ISZ  - NBC, 0), 69);
        const int vj = min(max(isxs - NBC, 0), 69);
        const float bv = vb[vi * 70 + vj] * 0.001f;
        g_bsrc[b * NS + tid] = bv * bv;
    }

    if (b == 0) {
        for (int t = tid; t < NT; t += 256) {
            float w = 0.f;
            if (t < 147) {
                const double a  = (73.0 - (double)t) * 15.0 * 0.001 * 3.141592653589793;
                const double be = a * a;
                w = (float)((1.0 - 2.0 * be) * exp(-be));
            }
            g_src[t] = w;
        }
    }
}

// ---------------- main: 8-CTA cluster per (b,s) field ----------------
__global__ void __launch_bounds__(TPB, 1) __cluster_dims__(CLUSTER, 1, 1)
fwi_kernel(float* __restrict__ out) {
    extern __shared__ float sm[];
    float* buf0 = sm;
    float* buf1 = sm + ROWS_S * SW;
    float* sT1  = sm + 2 * ROWS_S * SW;
    float* sT2  = sT1 + MAXNR * CW;
    float* sAL  = sT2 + MAXNR * CW;
    float* srcs = sAL + MAXNR * CW;

    const int tid  = threadIdx.x;
    const int cid  = blockIdx.x / CLUSTER;
    const unsigned int rank = my_ctarank();
    const int b = cid / NS, s = cid - b * NS;

    const int start = c_start[rank];
    const int nr    = c_nr[rank];
    const unsigned int rp = (rank + CLUSTER - 1) % CLUSTER;
    const unsigned int rn = (rank + 1) % CLUSTER;
    const int nr_p = c_nr[rp];

    // ---- init smem: zero fields, copy coeff slice + source wavelet ----
    for (int k = tid; k < 2 * ROWS_S * SW; k += TPB) sm[k] = 0.f;
    {
        const float* GT1 = g_temp1 + (b * HP + start) * CW;
        const float* GT2 = g_temp2 + (b * HP + start) * CW;
        const float* GAL = g_alpha + (b * HP + start) * CW;
        const int n = nr * CW;
        for (int k = tid; k < n; k += TPB) {
            sT1[k] = GT1[k];
            sT2[k] = GT2[k];
            sAL[k] = GAL[k];
        }
        for (int k = tid; k < NT; k += TPB) srcs[k] = g_src[k];
    }
    __syncthreads();

    const int li_src  = (ISZ >= start && ISZ < start + nr) ? (ISZ - start) : -1000;
    const int rec_row = (IGZ >= start && IGZ < start + nr) ? (IGZ - start + 2) : -1;
    const float bsrcv = g_bsrc[b * NS + s];
    const int isxs    = c_isx[s];
    float* __restrict__ orow = out + (size_t)(b * NS + s) * NT * NG;

    const float C2v = (float)( 4.0 / 3.0);
    const float C3v = (float)(-1.0 / 12.0);

    float* pold = buf0;   // p0 (t-1); pnew written here
    float* pcur = buf1;   // p1 (t)
    const unsigned int a0_u = smem_u32(buf0);
    const unsigned int a1_u = smem_u32(buf1);

    const int totG = nr * GPR;
    const int nXH  = nr * 4;
    const int nLoc = nXH + ((rec_row >= 0) ? NG : 0);

    for (int t = 0; t < NT; ++t) {
        const float srcval = bsrcv * srcs[t];

        // ---- phase A: pnew = temp1*p1 - temp2*p0 + alpha*lap(p1) ----
        for (int gi = tid; gi < totG; gi += TPB) {
            const int i  = gi / GPR;             // local interior row 0..nr-1
            const int g  = gi - i * GPR;
            const int j0 = g * 4;
            const int base = (i + 2) * SW + j0;  // smem x of logical j0-2

            const float4 a0 = *(const float4*)(pcur + base);
            const float4 a1 = *(const float4*)(pcur + base + 4);
            const float2 m2a = *(const float2*)(pcur + base - 2 * SW + 2);
            const float2 m2b = *(const float2*)(pcur + base - 2 * SW + 4);
            const float2 m1a = *(const float2*)(pcur + base -     SW + 2);
            const float2 m1b = *(const float2*)(pcur + base -     SW + 4);
            const float2 p1a = *(const float2*)(pcur + base +     SW + 2);
            const float2 p1b = *(const float2*)(pcur + base +     SW + 4);
            const float2 p2a = *(const float2*)(pcur + base + 2 * SW + 2);
            const float2 p2b = *(const float2*)(pcur + base + 2 * SW + 4);
            const float2 o0  = *(const float2*)(pold + base + 2);
            const float2 o1  = *(const float2*)(pold + base + 4);

            const int cb = i * CW + j0;
            const float4 t1 = *(const float4*)(sT1 + cb);
            const float4 t2 = *(const float4*)(sT2 + cb);
            const float4 al = *(const float4*)(sAL + cb);

            const float l0 = C2v * (a0.y + a0.w + m1a.x + p1a.x)
                           + C3v * (a0.x + a1.x + m2a.x + p2a.x);
            const float l1 = C2v * (a0.z + a1.x + m1a.y + p1a.y)
                           + C3v * (a0.y + a1.y + m2a.y + p2a.y);
            const float l2 = C2v * (a0.w + a1.y + m1b.x + p1b.x)
                           + C3v * (a0.z + a1.z + m2b.x + p2b.x);
            const float l3 = C2v * (a1.x + a1.z + m1b.y + p1b.y)
                           + C3v * (a0.w + a1.w + m2b.y + p2b.y);

            float n0 = t1.x * a0.z - t2.x * o0.x + al.x * l0;
            float n1 = t1.y * a0.w - t2.y * o0.y + al.y * l1;
            float n2 = t1.z * a1.x - t2.z * o1.x + al.z * l2;
            float n3 = t1.w * a1.y - t2.w * o1.y + al.w * l3;

            if (i == li_src) {
                const int d = isxs - j0;
                if      (d == 0) n0 += srcval;
                else if (d == 1) n1 += srcval;
                else if (d == 2) n2 += srcval;
                else if (d == 3) n3 += srcval;
            }

            *(float2*)(pold + base + 2) = make_float2(n0, n1);
            *(float2*)(pold + base + 4) = make_float2(n2, n3);
        }

        // ---- cluster arrive (release my writes), overlap local work w/ wait ----
        asm volatile("barrier.cluster.arrive.aligned;" ::: "memory");
        __syncthreads();   // local: all compute writes visible CTA-wide

        float* pn = pold;  // the freshly written buffer
        // local x-halo (periodic in x) + receiver recording
        for (int k = tid; k < nLoc; k += TPB) {
            if (k < nXH) {
                const int r = k >> 2, c = k & 3;
                const int row = r + 2;
                const int dc = (c < 2) ? c : 150 + c;    // 0,1,152,153
                const int sc = (c < 2) ? 150 + c : c;    // 150,151,2,3
                pn[row * SW + dc] = pn[row * SW + sc];
            } else {
                const int gg = k - nXH;
                orow[t * NG + gg] = pn[rec_row * SW + (NBC + gg + 2)];
            }
        }

        asm volatile("barrier.cluster.wait.aligned;" ::: "memory");

        // ---- DSMEM halo exchange: 2 rows from each z-neighbor (periodic) ----
        if (t < NT - 1) {
            const unsigned int pn_u = (t & 1) ? a1_u : a0_u;
            for (int k = tid; k < 600; k += TPB) {
                const int which = k / 150;
                const int x = k - which * 150 + 2;       // interior col 2..151
                int drow, srow; unsigned int rr;
                if (which < 2) { drow = which;      srow = nr_p + which; rr = rp; }
                else           { drow = nr + which; srow = which;        rr = rn; }
                const unsigned int raddr =
                    mapa_u32(pn_u + (unsigned int)(srow * SW + x) * 4u, rr);
                pn[drow * SW + x] = ld_cluster(raddr);
            }
        }
        __syncthreads();

        float* tmp = pold; pold = pcur; pcur = tmp;
    }
}

// ---------------- launch ----------------
extern "C" void kernel_launch(void* const* d_in, const int* in_sizes, int n_in,
                              void* d_out, int out_size) {
    const float* v = (const float*)d_in[0];
    float* out = (float*)d_out;

    cudaFuncSetAttribute(fwi_kernel, cudaFuncAttributeMaxDynamicSharedMemorySize,
                         SMEM_BYTES);

    fwi_init<<<2, 256>>>(v);
    fwi_kernel<<<2 * NS * CLUSTER, TPB, SMEM_BYTES>>>(out);
}